// round 4
// baseline (speedup 1.0000x reference)
#include <cuda_runtime.h>
#include <math_constants.h>

#define NPTS 4096
#define NV   3200
#define NF   6240
#define NCH  195            // 6240 / 32 chunks of 32 faces
#define W_INV 100.0f        // 1 / W_CONST
#define EPSF  1e-8f
#define PIF   3.14159265358979f
#define FULL  0xffffffffu

// Scratch (no allocations allowed)
// Per-face AoS: [v0x v0y v0z e1x][e1y e1z e2x e2y][e2z pad pad pad] as 3 float4
__device__ float4 g_tri4[3 * NF];
__device__ float  g_bb[6 * NCH];   // SoA: mnx mxx mny mxy mnz mxz

// ---------------------------------------------------------------------------
// Kernel 0: per-face v0/e1/e2 (AoS float4 x3) + per-32-face-chunk AABB
// ---------------------------------------------------------------------------
__global__ void prep(const float* __restrict__ verts,
                     const int*   __restrict__ faces) {
    int f = blockIdx.x * blockDim.x + threadIdx.x;
    if (f >= NF) return;
    int a = faces[f * 3 + 0], b = faces[f * 3 + 1], c = faces[f * 3 + 2];
    float ax = verts[a*3+0], ay = verts[a*3+1], az = verts[a*3+2];
    float bx = verts[b*3+0], by = verts[b*3+1], bz = verts[b*3+2];
    float cx = verts[c*3+0], cy = verts[c*3+1], cz = verts[c*3+2];

    float e1x = bx - ax, e1y = by - ay, e1z = bz - az;
    float e2x = cx - ax, e2y = cy - ay, e2z = cz - az;
    g_tri4[f*3+0] = make_float4(ax, ay, az, e1x);
    g_tri4[f*3+1] = make_float4(e1y, e1z, e2x, e2y);
    g_tri4[f*3+2] = make_float4(e2z, 0.0f, 0.0f, 0.0f);

    float mnx = fminf(ax, fminf(bx, cx)), mxx = fmaxf(ax, fmaxf(bx, cx));
    float mny = fminf(ay, fminf(by, cy)), mxy = fmaxf(ay, fmaxf(by, cy));
    float mnz = fminf(az, fminf(bz, cz)), mxz = fmaxf(az, fmaxf(bz, cz));
#pragma unroll
    for (int off = 16; off > 0; off >>= 1) {
        mnx = fminf(mnx, __shfl_down_sync(FULL, mnx, off));
        mxx = fmaxf(mxx, __shfl_down_sync(FULL, mxx, off));
        mny = fminf(mny, __shfl_down_sync(FULL, mny, off));
        mxy = fmaxf(mxy, __shfl_down_sync(FULL, mxy, off));
        mnz = fminf(mnz, __shfl_down_sync(FULL, mnz, off));
        mxz = fmaxf(mxz, __shfl_down_sync(FULL, mxz, off));
    }
    if ((threadIdx.x & 31) == 0) {
        int ch = f >> 5;
        g_bb[0*NCH+ch] = mnx - 1e-6f; g_bb[1*NCH+ch] = mxx + 1e-6f;
        g_bb[2*NCH+ch] = mny - 1e-6f; g_bb[3*NCH+ch] = mxy + 1e-6f;
        g_bb[4*NCH+ch] = mnz - 1e-6f; g_bb[5*NCH+ch] = mxz + 1e-6f;
    }
}

// Moller-Trumbore for face f against ray (p, d); returns t or +inf
__device__ __forceinline__ float mt_test(int f,
        float px, float py, float pz,
        float dx, float dy, float dz) {
    const float tol = 1e-6f;
    float4 q0 = g_tri4[f*3+0];
    float4 q1 = g_tri4[f*3+1];
    float4 q2 = g_tri4[f*3+2];
    float v0x = q0.x, v0y = q0.y, v0z = q0.z;
    float e1x = q0.w, e1y = q1.x, e1z = q1.y;
    float e2x = q1.z, e2y = q1.w, e2z = q2.x;

    float pvx = dy * e2z - dz * e2y;
    float pvy = dz * e2x - dx * e2z;
    float pvz = dx * e2y - dy * e2x;
    float det = fmaf(e1x, pvx, fmaf(e1y, pvy, e1z * pvz));
    float tc  = CUDART_INF_F;
    if (fabsf(det) > 1e-9f) {
        float invd = 1.0f / det;
        float tvx = px - v0x, tvy = py - v0y, tvz = pz - v0z;
        float u   = fmaf(tvx, pvx, fmaf(tvy, pvy, tvz * pvz)) * invd;
        float qvx = tvy * e1z - tvz * e1y;
        float qvy = tvz * e1x - tvx * e1z;
        float qvz = tvx * e1y - tvy * e1x;
        float vv  = fmaf(dx, qvx, fmaf(dy, qvy, dz * qvz)) * invd;
        float tt  = fmaf(e2x, qvx, fmaf(e2y, qvy, e2z * qvz)) * invd;
        if (u >= -tol && vv >= -tol && (u + vv) <= 1.0f + tol && tt > tol)
            tc = tt;
    }
    return tc;
}

// ---------------------------------------------------------------------------
// Kernel 1: fused windowed-kNN normal + ordered chunk-culled ray-tri.
// One warp per point, 8 points per CTA.
// ---------------------------------------------------------------------------
__global__ __launch_bounds__(256) void project(
        const float* __restrict__ x,
        const float* __restrict__ verts,
        const float* __restrict__ vnorm,
        float*       __restrict__ out) {
    __shared__ float sbb[6 * NCH];   // 4680 B
    for (int i = threadIdx.x; i < 6 * NCH; i += 256)
        sbb[i] = g_bb[i];
    __syncthreads();

    const int lane = threadIdx.x & 31;
    const int pt   = blockIdx.x * 8 + (threadIdx.x >> 5);

    const float px = x[pt*3+0], py = x[pt*3+1], pz = x[pt*3+2];

    // ---- windowed kNN: 5(theta) x 9(phi) window is exact for top-8 ----
    const float DTH = 0.9f * PIF / 39.0f;
    const float TH0 = 0.05f * PIF;
    const float DPH = 2.0f * PIF / 80.0f;
    float rr  = sqrtf(fmaf(px, px, fmaf(py, py, pz * pz)));
    float th  = acosf(pz / rr);
    float ph  = atan2f(py, px);
    if (ph < 0.0f) ph += 2.0f * PIF;
    int i0 = __float2int_rn((th - TH0) / DTH);
    int j0 = __float2int_rn(ph / DPH);
    if (j0 >= 80) j0 -= 80;

    float bd[2]; int bi[2];
    bd[0] = CUDART_INF_F; bd[1] = CUDART_INF_F; bi[0] = 0; bi[1] = 0;

#pragma unroll
    for (int r = 0; r < 2; ++r) {
        int k = r * 32 + lane;
        float d2 = CUDART_INF_F;
        int vidx = 0;
        if (k < 45) {
            int di = k / 9 - 2;
            int dj = k % 9 - 4;
            int ii = i0 + di;
            int jj = j0 + dj;
            jj += (jj < 0) ? 80 : 0;
            jj -= (jj >= 80) ? 80 : 0;
            if (ii >= 0 && ii < 40) {
                vidx = ii * 80 + jj;
                float dx = verts[vidx*3+0] - px;
                float dy = verts[vidx*3+1] - py;
                float dz = verts[vidx*3+2] - pz;
                d2 = fmaf(dx, dx, fmaf(dy, dy, dz * dz));
            }
        }
        if (d2 < bd[1]) {
            bd[1] = d2; bi[1] = vidx;
            if (bd[1] < bd[0]) {
                float td = bd[0]; bd[0] = bd[1]; bd[1] = td;
                int   ti = bi[0]; bi[0] = bi[1]; bi[1] = ti;
            }
        }
    }

    // ---- 8-round REDUX argmin merge; round r parks winner in lane r ----
    float myd2 = EPSF;
    int   myidx = 0;
#pragma unroll
    for (int r = 0; r < 8; ++r) {
        unsigned key  = __float_as_uint(bd[0]);       // non-negative: bits monotone
        unsigned kmin = __reduce_min_sync(FULL, key);
        unsigned bal  = __ballot_sync(FULL, key == kmin);
        int l = __ffs(bal) - 1;
        int widx = __shfl_sync(FULL, bi[0], l);
        if (lane == r) { myd2 = __uint_as_float(kmin); myidx = widx; }
        if (lane == l) { bd[0] = bd[1]; bi[0] = bi[1]; bd[1] = CUDART_INF_F; }
    }

    // ---- parallel weighted-normal accumulation on lanes 0..7 ----
    float w = 0.0f, ax = 0.0f, ay = 0.0f, az = 0.0f;
    if (lane < 8) {
        float d2c = fmaxf(myd2, EPSF);
        w  = 1.0f / d2c;
        ax = w * vnorm[myidx*3+0];
        ay = w * vnorm[myidx*3+1];
        az = w * vnorm[myidx*3+2];
    }
#pragma unroll
    for (int off = 4; off > 0; off >>= 1) {
        w  += __shfl_xor_sync(FULL, w,  off);
        ax += __shfl_xor_sync(FULL, ax, off);
        ay += __shfl_xor_sync(FULL, ay, off);
        az += __shfl_xor_sync(FULL, az, off);
    }
    float sumw = __shfl_sync(FULL, w,  0);
    float snx  = __shfl_sync(FULL, ax, 0);
    float sny  = __shfl_sync(FULL, ay, 0);
    float snz  = __shfl_sync(FULL, az, 0);
    int   iv1  = __shfl_sync(FULL, myidx, 0);
    float d20  = fmaxf(__shfl_sync(FULL, myd2, 0), EPSF);

    float v1x = verts[iv1*3+0], v1y = verts[iv1*3+1], v1z = verts[iv1*3+2];
    float cc  = W_INV / d20;
    float ntx = snx + (px - v1x) * cc;
    float nty = sny + (py - v1y) * cc;
    float ntz = snz + (pz - v1z) * cc;
    float W   = sumw + W_INV;
    ntx /= W; nty /= W; ntz /= W;
    float nrm = sqrtf(fmaf(ntx, ntx, fmaf(nty, nty, ntz * ntz)));
    float inv = 1.0f / (nrm + 1e-8f);
    float nx = ntx * inv, ny = nty * inv, nz = ntz * inv;
    float dx = -nx, dy = -ny, dz = -nz;

    // ---- slab-test all 195 chunks into 7 per-lane tn registers ----
    const float tol = 1e-6f;
    float ivx = 1.0f / dx, ivy = 1.0f / dy, ivz = 1.0f / dz;
    float tnr[7];
#pragma unroll
    for (int s = 0; s < 7; ++s) {
        int ch = s * 32 + lane;
        float res = CUDART_INF_F;
        if (ch < NCH) {
            float t0 = (sbb[0*NCH+ch] - px) * ivx;
            float t1 = (sbb[1*NCH+ch] - px) * ivx;
            float tn = fminf(t0, t1), tf = fmaxf(t0, t1);
            t0 = (sbb[2*NCH+ch] - py) * ivy;
            t1 = (sbb[3*NCH+ch] - py) * ivy;
            tn = fmaxf(tn, fminf(t0, t1)); tf = fminf(tf, fmaxf(t0, t1));
            t0 = (sbb[4*NCH+ch] - pz) * ivz;
            t1 = (sbb[5*NCH+ch] - pz) * ivz;
            tn = fmaxf(tn, fminf(t0, t1)); tf = fminf(tf, fmaxf(t0, t1));
            if (tf >= fmaxf(tn, tol)) res = fmaxf(tn, 0.0f);   // priority key
        }
        tnr[s] = res;
    }

    // ---- ordered traversal, TWO nearest chunks per iteration ----
    float tmin = CUDART_INF_F;
    while (true) {
        // nearest surviving chunk
        float mytn = tnr[0];
        int myslot = 0;
#pragma unroll
        for (int s = 1; s < 7; ++s)
            if (tnr[s] < mytn) { mytn = tnr[s]; myslot = s; }
        unsigned k1 = __reduce_min_sync(FULL, __float_as_uint(mytn));
        if (__uint_as_float(k1) >= tmin) break;   // nothing can improve
        unsigned bal1 = __ballot_sync(FULL, __float_as_uint(mytn) == k1);
        int l1 = __ffs(bal1) - 1;
        int ws1 = __shfl_sync(FULL, myslot, l1);
        int ch1 = ws1 * 32 + l1;
        if (lane == l1) tnr[myslot] = CUDART_INF_F;

        // second-nearest surviving chunk
        float mytn2 = tnr[0];
        int myslot2 = 0;
#pragma unroll
        for (int s = 1; s < 7; ++s)
            if (tnr[s] < mytn2) { mytn2 = tnr[s]; myslot2 = s; }
        unsigned k2 = __reduce_min_sync(FULL, __float_as_uint(mytn2));
        bool have2 = (__uint_as_float(k2) < tmin);
        int ch2 = 0;
        if (have2) {
            unsigned bal2 = __ballot_sync(FULL, __float_as_uint(mytn2) == k2);
            int l2 = __ffs(bal2) - 1;
            int ws2 = __shfl_sync(FULL, myslot2, l2);
            ch2 = ws2 * 32 + l2;
            if (lane == l2) tnr[myslot2] = CUDART_INF_F;
        }

        float tc = mt_test(ch1 * 32 + lane, px, py, pz, dx, dy, dz);
        if (have2)
            tc = fminf(tc, mt_test(ch2 * 32 + lane, px, py, pz, dx, dy, dz));

        unsigned tb = __reduce_min_sync(FULL, __float_as_uint(fminf(tmin, tc)));
        tmin = __uint_as_float(tb);
    }

    if (lane == 0) {
        float tm = (tmin < 1e30f) ? tmin : 0.0f;
        float xcx = fmaf(tm, dx, px);
        float xcy = fmaf(tm, dy, py);
        float xcz = fmaf(tm, dz, pz);
        out[pt*3+0] = xcx;
        out[pt*3+1] = xcy;
        out[pt*3+2] = xcz;
        float s = fmaf(px - xcx, nx, fmaf(py - xcy, ny, (pz - xcz) * nz));
        out[NPTS*3 + pt] = s;
        out[NPTS*4 + pt*3+0] = nx;
        out[NPTS*4 + pt*3+1] = ny;
        out[NPTS*4 + pt*3+2] = nz;
    }
}

// ---------------------------------------------------------------------------
extern "C" void kernel_launch(void* const* d_in, const int* in_sizes, int n_in,
                              void* d_out, int out_size) {
    const float* x     = (const float*)d_in[0];
    const float* verts = (const float*)d_in[1];
    const float* vnorm = (const float*)d_in[2];
    const int*   faces = (const int*)d_in[3];
    float*       out   = (float*)d_out;

    prep<<<(NF + 255) / 256, 256>>>(verts, faces);
    project<<<NPTS / 8, 256>>>(x, verts, vnorm, out);
}